// round 13
// baseline (speedup 1.0000x reference)
#include <cuda_runtime.h>
#include <math.h>

#define INSIZE     1024
#define NREFL      40          // 20 U + 20 V, in application order
#define NBLK       4
#define BLKR       10          // reflectors per block
#define BATCH      32768
#define ROWS_PW    4
#define NBATCH     (BATCH / ROWS_PW)

// Scratch (no device allocs allowed)
__device__ float g_sigma[INSIZE];
__device__ float g_c[NREFL];                 // c_k = 2/||y_k||^2, app order
__device__ float g_G[NBLK][BLKR * BLKR];     // Gs[m][j] = c_j * (y_m . y_j), m<j
__device__ unsigned int g_work;

typedef unsigned long long ull;

// Packed fp32x2 FMA (Blackwell FFMA2).
__device__ __forceinline__ ull ffma2(ull a, ull b, ull c) {
    ull d;
    asm("fma.rn.f32x2 %0, %1, %2, %3;" : "=l"(d) : "l"(a), "l"(b), "l"(c));
    return d;
}

union F4U {
    float4 f;
    ull p[2];
    float s[4];
};

// Reflector row k (application order) -> source pointer.
// k 0..19 : U row k.   k 20..39 : V row (39-k)  (V applied 19 .. 0).
__device__ __forceinline__ const float* yrow(int k, const float* U,
                                             const float* V) {
    return (k < 20) ? (U + (size_t)k * INSIZE)
                    : (V + (size_t)(39 - k) * INSIZE);
}

// ---------------------------------------------------------------------------
// Prep: sigma, c_k, scaled Gram per block, reset work queue.  1024 threads.
// ---------------------------------------------------------------------------
__global__ void prep_kernel(const float* __restrict__ U,
                            const float* __restrict__ p,
                            const float* __restrict__ V) {
    __shared__ float sc[NREFL];          // c_k, application order

    const int tid  = threadIdx.x;
    const int w    = tid >> 5;
    const int lane = tid & 31;

    if (tid == 0) g_work = 0u;

    if (tid < INSIZE) {
        float pv = p[tid];
        float s = 1.0f / (1.0f + expf(-pv));
        g_sigma[tid] = 0.4f * s + 0.6f;  // 2R(sigmoid-0.5)+mean, R=0.2
    }

    // Norms: warp w (<20) handles U row w (app idx w) and V row w (app 39-w).
    if (w < 20) {
        float su = 0.0f, sv = 0.0f;
        for (int j = lane; j < INSIZE; j += 32) {
            float uu = U[(size_t)w * INSIZE + j]; su += uu * uu;
            float vv = V[(size_t)w * INSIZE + j]; sv += vv * vv;
        }
        #pragma unroll
        for (int off = 16; off; off >>= 1) {
            su += __shfl_xor_sync(0xffffffffu, su, off);
            sv += __shfl_xor_sync(0xffffffffu, sv, off);
        }
        if (lane == 0) {
            sc[w]      = 2.0f / su;
            sc[39 - w] = 2.0f / sv;
        }
    }
    __syncthreads();

    if (tid < NREFL) g_c[tid] = sc[tid];

    // Scaled Gram: flat space of 400 slots (b, m, j); only m < j computed.
    // One warp per slot, strided.
    for (int pid = w; pid < NBLK * BLKR * BLKR; pid += 32) {
        int b   = pid / (BLKR * BLKR);
        int rem = pid % (BLKR * BLKR);
        int m   = rem / BLKR;
        int j   = rem % BLKR;
        if (m >= j) continue;
        const float* ym = yrow(b * BLKR + m, U, V);
        const float* yj = yrow(b * BLKR + j, U, V);
        float s = 0.0f;
        for (int e = lane; e < INSIZE; e += 32) s += ym[e] * yj[e];
        #pragma unroll
        for (int off = 16; off; off >>= 1)
            s += __shfl_xor_sync(0xffffffffu, s, off);
        if (lane == 0) g_G[b][rem] = s * sc[b * BLKR + j];
    }
}

// ---------------------------------------------------------------------------
// Main: persistent, 1 CTA/SM, rows in registers, blocked reflector apply.
// ---------------------------------------------------------------------------
extern __shared__ float smem[];

// Apply one block of 10 reflectors to 4 register-resident rows.
__device__ __forceinline__ void block_apply(F4U xr[ROWS_PW][8],
                                            const float* __restrict__ sYb,
                                            const float* __restrict__ sGb,
                                            const float* __restrict__ sCb,
                                            int lane) {
    float d[ROWS_PW][BLKR];

    // ---- raw dots d[r][c] = x_r . y_c  (40 independent, lane partials) ----
    #pragma unroll
    for (int c = 0; c < BLKR; c++) {
        F4U yf[8];
        const float4* yp = reinterpret_cast<const float4*>(sYb + c * INSIZE);
        #pragma unroll
        for (int j = 0; j < 8; j++) yf[j].f = yp[lane + 32 * j];
        #pragma unroll
        for (int pr = 0; pr < 2; pr++) {
            const int r0 = pr * 2, r1 = pr * 2 + 1;
            ull a0 = 0ull, a1 = 0ull, b0 = 0ull, b1 = 0ull;
            #pragma unroll
            for (int j = 0; j < 8; j++) {
                a0 = ffma2(xr[r0][j].p[0], yf[j].p[0], a0);
                a1 = ffma2(xr[r0][j].p[1], yf[j].p[1], a1);
                b0 = ffma2(xr[r1][j].p[0], yf[j].p[0], b0);
                b1 = ffma2(xr[r1][j].p[1], yf[j].p[1], b1);
            }
            F4U ta; ta.p[0] = a0; ta.p[1] = a1;
            d[r0][c] = (ta.s[0] + ta.s[2]) + (ta.s[1] + ta.s[3]);
            F4U tb; tb.p[0] = b0; tb.p[1] = b1;
            d[r1][c] = (tb.s[0] + tb.s[2]) + (tb.s[1] + tb.s[3]);
        }
    }

    // ---- batched butterfly: 40 independent shuffles per stage ----
    #pragma unroll
    for (int off = 16; off; off >>= 1) {
        #pragma unroll
        for (int r = 0; r < ROWS_PW; r++)
            #pragma unroll
            for (int c = 0; c < BLKR; c++)
                d[r][c] += __shfl_xor_sync(0xffffffffu, d[r][c], off);
    }

    // ---- forward substitution (exact sequential algorithm, dots hoisted):
    //      s_j = c_j * d_j - sum_{m<j} Gs[m][j] * s_m,  Gs pre-scaled by c_j.
    //      d[][] is overwritten in place with s.
    #pragma unroll
    for (int j = 0; j < BLKR; j++) {
        const float cj = sCb[j];
        float a0 = cj * d[0][j];
        float a1 = cj * d[1][j];
        float a2 = cj * d[2][j];
        float a3 = cj * d[3][j];
        #pragma unroll
        for (int m = 0; m < j; m++) {
            const float g = sGb[m * BLKR + j];
            a0 -= g * d[0][m];
            a1 -= g * d[1][m];
            a2 -= g * d[2][m];
            a3 -= g * d[3][m];
        }
        d[0][j] = a0; d[1][j] = a1; d[2][j] = a2; d[3][j] = a3;
    }

    // ---- x -= s_c * y_c  (40 independent axpys) ----
    #pragma unroll
    for (int c = 0; c < BLKR; c++) {
        F4U yf[8];
        const float4* yp = reinterpret_cast<const float4*>(sYb + c * INSIZE);
        #pragma unroll
        for (int j = 0; j < 8; j++) yf[j].f = yp[lane + 32 * j];
        #pragma unroll
        for (int r = 0; r < ROWS_PW; r++) {
            F4U na; na.s[0] = -d[r][c]; na.s[1] = na.s[0];
            #pragma unroll
            for (int j = 0; j < 8; j++) {
                xr[r][j].p[0] = ffma2(yf[j].p[0], na.p[0], xr[r][j].p[0]);
                xr[r][j].p[1] = ffma2(yf[j].p[1], na.p[0], xr[r][j].p[1]);
            }
        }
    }
}

__global__ void __launch_bounds__(256, 1)
spectral_kernel(const float* __restrict__ x,
                const float* __restrict__ U,
                const float* __restrict__ V,
                const float* __restrict__ bias,
                float* __restrict__ out) {
    float* sY    = smem;                          // 40*1024
    float* sSig  = sY + NREFL * INSIZE;           // 1024
    float* sBias = sSig + INSIZE;                 // 1024
    float* sG    = sBias + INSIZE;                // 400
    float* sC    = sG + NBLK * BLKR * BLKR;       // 40

    const int tid = threadIdx.x;

    // Stage reflectors in application order (V rows reversed).
    for (int idx = tid; idx < NREFL * (INSIZE / 4); idx += 256) {
        int row = idx >> 8;              // 256 float4 per row
        int c4  = idx & 255;
        const float4* src = reinterpret_cast<const float4*>(yrow(row, U, V));
        reinterpret_cast<float4*>(sY)[idx] = src[c4];
    }
    if (tid < 256) {
        reinterpret_cast<float4*>(sSig)[tid]  =
            reinterpret_cast<const float4*>(g_sigma)[tid];
        reinterpret_cast<float4*>(sBias)[tid] =
            reinterpret_cast<const float4*>(bias)[tid];
    }
    // FIX: 400 Gram entries > 256 threads — must stride, not predicate.
    for (int i = tid; i < NBLK * BLKR * BLKR; i += 256)
        sG[i] = (&g_G[0][0])[i];
    if (tid < NREFL) sC[tid] = g_c[tid];
    __syncthreads();

    const int lane = tid & 31;

    for (;;) {
        unsigned int b;
        if (lane == 0) b = atomicAdd(&g_work, 1u);
        b = __shfl_sync(0xffffffffu, b, 0);
        if (b >= NBATCH) break;

        const int row0 = (int)b * ROWS_PW;

        F4U xr[ROWS_PW][8];
        #pragma unroll
        for (int r = 0; r < ROWS_PW; r++) {
            const float4* xp =
                reinterpret_cast<const float4*>(x + (size_t)(row0 + r) * INSIZE);
            #pragma unroll
            for (int j = 0; j < 8; j++) xr[r][j].f = xp[lane + 32 * j];
        }

        #pragma unroll 1
        for (int blk = 0; blk < NBLK; blk++) {
            if (blk == 2) {
                // diagonal sigma between U and V phases
                const float4* sp = reinterpret_cast<const float4*>(sSig);
                #pragma unroll
                for (int j = 0; j < 8; j++) {
                    float4 sg = sp[lane + 32 * j];
                    #pragma unroll
                    for (int r = 0; r < ROWS_PW; r++) {
                        xr[r][j].s[0] *= sg.x; xr[r][j].s[1] *= sg.y;
                        xr[r][j].s[2] *= sg.z; xr[r][j].s[3] *= sg.w;
                    }
                }
            }
            block_apply(xr, sY + (size_t)blk * BLKR * INSIZE,
                        sG + blk * BLKR * BLKR, sC + blk * BLKR, lane);
        }

        // bias add + store
        #pragma unroll
        for (int r = 0; r < ROWS_PW; r++) {
            float4* op =
                reinterpret_cast<float4*>(out + (size_t)(row0 + r) * INSIZE);
            const float4* bp = reinterpret_cast<const float4*>(sBias);
            #pragma unroll
            for (int j = 0; j < 8; j++) {
                float4 v = xr[r][j].f;
                float4 bb = bp[lane + 32 * j];
                v.x += bb.x; v.y += bb.y; v.z += bb.z; v.w += bb.w;
                op[lane + 32 * j] = v;
            }
        }
    }
}

// ---------------------------------------------------------------------------
extern "C" void kernel_launch(void* const* d_in, const int* in_sizes, int n_in,
                              void* d_out, int out_size) {
    const float* x    = (const float*)d_in[0];
    const float* U    = (const float*)d_in[1];
    const float* p    = (const float*)d_in[2];
    const float* V    = (const float*)d_in[3];
    const float* bias = (const float*)d_in[4];
    float* out = (float*)d_out;

    (void)in_sizes; (void)n_in; (void)out_size;

    prep_kernel<<<1, 1024>>>(U, p, V);

    int nsm = 148;
    cudaDeviceGetAttribute(&nsm, cudaDevAttrMultiProcessorCount, 0);

    size_t smem_bytes =
        (size_t)(NREFL * INSIZE + 2 * INSIZE + NBLK * BLKR * BLKR + NREFL) *
        sizeof(float);
    cudaFuncSetAttribute(spectral_kernel,
                         cudaFuncAttributeMaxDynamicSharedMemorySize,
                         (int)smem_bytes);

    spectral_kernel<<<nsm, 256, smem_bytes>>>(x, U, V, bias, out);
}

// round 14
// speedup vs baseline: 1.2572x; 1.2572x over previous
#include <cuda_runtime.h>
#include <math.h>

#define INSIZE     1024
#define NREFL      40          // 20 U + 20 V, in application order
#define NBLK       8
#define BLKR       5           // reflectors per block (small => no spills)
#define BATCH      32768
#define ROWS_PW    4
#define NBATCH     (BATCH / ROWS_PW)

// Scratch (no device allocs allowed)
__device__ float g_sigma[INSIZE];
__device__ float g_c[NREFL];                 // c_k = 2/||y_k||^2, app order
__device__ float g_G[NBLK][BLKR * BLKR];     // Gs[m][j] = c_j * (y_m . y_j), m<j
__device__ unsigned int g_work;

typedef unsigned long long ull;

// Packed fp32x2 FMA (Blackwell FFMA2).
__device__ __forceinline__ ull ffma2(ull a, ull b, ull c) {
    ull d;
    asm("fma.rn.f32x2 %0, %1, %2, %3;" : "=l"(d) : "l"(a), "l"(b), "l"(c));
    return d;
}

union F4U {
    float4 f;
    ull p[2];
    float s[4];
};

// Reflector row k (application order) -> source pointer.
// k 0..19 : U row k.   k 20..39 : V row (39-k)  (V applied 19 .. 0).
__device__ __forceinline__ const float* yrow(int k, const float* U,
                                             const float* V) {
    return (k < 20) ? (U + (size_t)k * INSIZE)
                    : (V + (size_t)(39 - k) * INSIZE);
}

// ---------------------------------------------------------------------------
// Prep: sigma, c_k, scaled Gram per block, reset work queue.  1024 threads.
// ---------------------------------------------------------------------------
__global__ void prep_kernel(const float* __restrict__ U,
                            const float* __restrict__ p,
                            const float* __restrict__ V) {
    __shared__ float sc[NREFL];          // c_k, application order

    const int tid  = threadIdx.x;
    const int w    = tid >> 5;
    const int lane = tid & 31;

    if (tid == 0) g_work = 0u;

    if (tid < INSIZE) {
        float pv = p[tid];
        float s = 1.0f / (1.0f + expf(-pv));
        g_sigma[tid] = 0.4f * s + 0.6f;  // 2R(sigmoid-0.5)+mean, R=0.2
    }

    // Norms: warp w (<20) handles U row w (app idx w) and V row w (app 39-w).
    if (w < 20) {
        float su = 0.0f, sv = 0.0f;
        for (int j = lane; j < INSIZE; j += 32) {
            float uu = U[(size_t)w * INSIZE + j]; su += uu * uu;
            float vv = V[(size_t)w * INSIZE + j]; sv += vv * vv;
        }
        #pragma unroll
        for (int off = 16; off; off >>= 1) {
            su += __shfl_xor_sync(0xffffffffu, su, off);
            sv += __shfl_xor_sync(0xffffffffu, sv, off);
        }
        if (lane == 0) {
            sc[w]      = 2.0f / su;
            sc[39 - w] = 2.0f / sv;
        }
    }
    __syncthreads();

    if (tid < NREFL) g_c[tid] = sc[tid];

    // Scaled Gram: flat space of NBLK*25 slots (b, m, j); only m < j computed.
    // One warp per slot, strided.
    for (int pid = w; pid < NBLK * BLKR * BLKR; pid += 32) {
        int b   = pid / (BLKR * BLKR);
        int rem = pid % (BLKR * BLKR);
        int m   = rem / BLKR;
        int j   = rem % BLKR;
        if (m >= j) continue;
        const float* ym = yrow(b * BLKR + m, U, V);
        const float* yj = yrow(b * BLKR + j, U, V);
        float s = 0.0f;
        for (int e = lane; e < INSIZE; e += 32) s += ym[e] * yj[e];
        #pragma unroll
        for (int off = 16; off; off >>= 1)
            s += __shfl_xor_sync(0xffffffffu, s, off);
        if (lane == 0) g_G[b][rem] = s * sc[b * BLKR + j];
    }
}

// ---------------------------------------------------------------------------
// Main: persistent, 1 CTA/SM, rows in registers, blocked reflector apply.
// ---------------------------------------------------------------------------
extern __shared__ float smem[];

// Apply one block of 5 reflectors to 4 register-resident rows.
__device__ __forceinline__ void block_apply(F4U xr[ROWS_PW][8],
                                            const float* __restrict__ sYb,
                                            const float* __restrict__ sGb,
                                            const float* __restrict__ sCb,
                                            int lane) {
    float d[ROWS_PW][BLKR];

    // ---- raw dots d[r][c] = x_r . y_c  (20 independent, lane partials) ----
    #pragma unroll
    for (int c = 0; c < BLKR; c++) {
        F4U yf[8];
        const float4* yp = reinterpret_cast<const float4*>(sYb + c * INSIZE);
        #pragma unroll
        for (int j = 0; j < 8; j++) yf[j].f = yp[lane + 32 * j];
        #pragma unroll
        for (int pr = 0; pr < 2; pr++) {
            const int r0 = pr * 2, r1 = pr * 2 + 1;
            ull a0 = 0ull, a1 = 0ull, b0 = 0ull, b1 = 0ull;
            #pragma unroll
            for (int j = 0; j < 8; j++) {
                a0 = ffma2(xr[r0][j].p[0], yf[j].p[0], a0);
                a1 = ffma2(xr[r0][j].p[1], yf[j].p[1], a1);
                b0 = ffma2(xr[r1][j].p[0], yf[j].p[0], b0);
                b1 = ffma2(xr[r1][j].p[1], yf[j].p[1], b1);
            }
            F4U ta; ta.p[0] = a0; ta.p[1] = a1;
            d[r0][c] = (ta.s[0] + ta.s[2]) + (ta.s[1] + ta.s[3]);
            F4U tb; tb.p[0] = b0; tb.p[1] = b1;
            d[r1][c] = (tb.s[0] + tb.s[2]) + (tb.s[1] + tb.s[3]);
        }
    }

    // ---- batched butterfly: 20 independent shuffles per stage ----
    #pragma unroll
    for (int off = 16; off; off >>= 1) {
        #pragma unroll
        for (int r = 0; r < ROWS_PW; r++)
            #pragma unroll
            for (int c = 0; c < BLKR; c++)
                d[r][c] += __shfl_xor_sync(0xffffffffu, d[r][c], off);
    }

    // ---- forward substitution (exact sequential algorithm, dots hoisted):
    //      s_j = c_j * d_j - sum_{m<j} Gs[m][j] * s_m,  Gs pre-scaled by c_j.
    //      d[][] is overwritten in place with s.
    #pragma unroll
    for (int j = 0; j < BLKR; j++) {
        const float cj = sCb[j];
        float a0 = cj * d[0][j];
        float a1 = cj * d[1][j];
        float a2 = cj * d[2][j];
        float a3 = cj * d[3][j];
        #pragma unroll
        for (int m = 0; m < j; m++) {
            const float g = sGb[m * BLKR + j];
            a0 -= g * d[0][m];
            a1 -= g * d[1][m];
            a2 -= g * d[2][m];
            a3 -= g * d[3][m];
        }
        d[0][j] = a0; d[1][j] = a1; d[2][j] = a2; d[3][j] = a3;
    }

    // ---- x -= s_c * y_c  (20 independent axpys) ----
    #pragma unroll
    for (int c = 0; c < BLKR; c++) {
        F4U yf[8];
        const float4* yp = reinterpret_cast<const float4*>(sYb + c * INSIZE);
        #pragma unroll
        for (int j = 0; j < 8; j++) yf[j].f = yp[lane + 32 * j];
        #pragma unroll
        for (int r = 0; r < ROWS_PW; r++) {
            F4U na; na.s[0] = -d[r][c]; na.s[1] = na.s[0];
            #pragma unroll
            for (int j = 0; j < 8; j++) {
                xr[r][j].p[0] = ffma2(yf[j].p[0], na.p[0], xr[r][j].p[0]);
                xr[r][j].p[1] = ffma2(yf[j].p[1], na.p[0], xr[r][j].p[1]);
            }
        }
    }
}

__global__ void __launch_bounds__(256, 1)
spectral_kernel(const float* __restrict__ x,
                const float* __restrict__ U,
                const float* __restrict__ V,
                const float* __restrict__ bias,
                float* __restrict__ out) {
    float* sY    = smem;                          // 40*1024
    float* sSig  = sY + NREFL * INSIZE;           // 1024
    float* sBias = sSig + INSIZE;                 // 1024
    float* sG    = sBias + INSIZE;                // NBLK*25 = 200
    float* sC    = sG + NBLK * BLKR * BLKR;       // 40

    const int tid = threadIdx.x;

    // Stage reflectors in application order (V rows reversed).
    for (int idx = tid; idx < NREFL * (INSIZE / 4); idx += 256) {
        int row = idx >> 8;              // 256 float4 per row
        int c4  = idx & 255;
        const float4* src = reinterpret_cast<const float4*>(yrow(row, U, V));
        reinterpret_cast<float4*>(sY)[idx] = src[c4];
    }
    if (tid < 256) {
        reinterpret_cast<float4*>(sSig)[tid]  =
            reinterpret_cast<const float4*>(g_sigma)[tid];
        reinterpret_cast<float4*>(sBias)[tid] =
            reinterpret_cast<const float4*>(bias)[tid];
    }
    for (int i = tid; i < NBLK * BLKR * BLKR; i += 256)
        sG[i] = (&g_G[0][0])[i];
    if (tid < NREFL) sC[tid] = g_c[tid];
    __syncthreads();

    const int lane = tid & 31;

    for (;;) {
        unsigned int b;
        if (lane == 0) b = atomicAdd(&g_work, 1u);
        b = __shfl_sync(0xffffffffu, b, 0);
        if (b >= NBATCH) break;

        const int row0 = (int)b * ROWS_PW;

        F4U xr[ROWS_PW][8];
        #pragma unroll
        for (int r = 0; r < ROWS_PW; r++) {
            const float4* xp =
                reinterpret_cast<const float4*>(x + (size_t)(row0 + r) * INSIZE);
            #pragma unroll
            for (int j = 0; j < 8; j++) xr[r][j].f = xp[lane + 32 * j];
        }

        #pragma unroll 1
        for (int blk = 0; blk < NBLK; blk++) {
            if (blk == NBLK / 2) {
                // diagonal sigma between U and V phases
                const float4* sp = reinterpret_cast<const float4*>(sSig);
                #pragma unroll
                for (int j = 0; j < 8; j++) {
                    float4 sg = sp[lane + 32 * j];
                    #pragma unroll
                    for (int r = 0; r < ROWS_PW; r++) {
                        xr[r][j].s[0] *= sg.x; xr[r][j].s[1] *= sg.y;
                        xr[r][j].s[2] *= sg.z; xr[r][j].s[3] *= sg.w;
                    }
                }
            }
            block_apply(xr, sY + (size_t)blk * BLKR * INSIZE,
                        sG + blk * BLKR * BLKR, sC + blk * BLKR, lane);
        }

        // bias add + store
        #pragma unroll
        for (int r = 0; r < ROWS_PW; r++) {
            float4* op =
                reinterpret_cast<float4*>(out + (size_t)(row0 + r) * INSIZE);
            const float4* bp = reinterpret_cast<const float4*>(sBias);
            #pragma unroll
            for (int j = 0; j < 8; j++) {
                float4 v = xr[r][j].f;
                float4 bb = bp[lane + 32 * j];
                v.x += bb.x; v.y += bb.y; v.z += bb.z; v.w += bb.w;
                op[lane + 32 * j] = v;
            }
        }
    }
}

// ---------------------------------------------------------------------------
extern "C" void kernel_launch(void* const* d_in, const int* in_sizes, int n_in,
                              void* d_out, int out_size) {
    const float* x    = (const float*)d_in[0];
    const float* U    = (const float*)d_in[1];
    const float* p    = (const float*)d_in[2];
    const float* V    = (const float*)d_in[3];
    const float* bias = (const float*)d_in[4];
    float* out = (float*)d_out;

    (void)in_sizes; (void)n_in; (void)out_size;

    prep_kernel<<<1, 1024>>>(U, p, V);

    int nsm = 148;
    cudaDeviceGetAttribute(&nsm, cudaDevAttrMultiProcessorCount, 0);

    size_t smem_bytes =
        (size_t)(NREFL * INSIZE + 2 * INSIZE + NBLK * BLKR * BLKR + NREFL) *
        sizeof(float);
    cudaFuncSetAttribute(spectral_kernel,
                         cudaFuncAttributeMaxDynamicSharedMemorySize,
                         (int)smem_bytes);

    spectral_kernel<<<nsm, 256, smem_bytes>>>(x, U, V, bias, out);
}

// round 15
// speedup vs baseline: 1.7068x; 1.3576x over previous
#include <cuda_runtime.h>
#include <math.h>

#define INSIZE     1024
#define NREFL      40          // 20 U + 20 V, in application order
#define NBLK       8
#define BLKR       5           // reflectors per block
#define BATCH      32768
#define ROWS_PW    4
#define NBATCH     (BATCH / ROWS_PW)

// Scratch (no device allocs allowed)
__device__ float g_sigma[INSIZE];
__device__ float g_c[NREFL];                 // c_k = 2/||y_k||^2, app order
__device__ float g_G[NBLK][BLKR * BLKR];     // Gs[m][j] = c_j * (y_m . y_j), m<j
__device__ unsigned int g_work;

typedef unsigned long long ull;

// Packed fp32x2 FMA (Blackwell FFMA2).
__device__ __forceinline__ ull ffma2(ull a, ull b, ull c) {
    ull d;
    asm("fma.rn.f32x2 %0, %1, %2, %3;" : "=l"(d) : "l"(a), "l"(b), "l"(c));
    return d;
}

union F4U {
    float4 f;
    ull p[2];
    float s[4];
};

union U2 {
    ull u;
    float f[2];
};

// Reflector row k (application order) -> source pointer.
// k 0..19 : U row k.   k 20..39 : V row (39-k)  (V applied 19 .. 0).
__device__ __forceinline__ const float* yrow(int k, const float* U,
                                             const float* V) {
    return (k < 20) ? (U + (size_t)k * INSIZE)
                    : (V + (size_t)(39 - k) * INSIZE);
}

// ---------------------------------------------------------------------------
// Prep: sigma, c_k, scaled Gram per block, reset work queue.  1024 threads.
// ---------------------------------------------------------------------------
__global__ void prep_kernel(const float* __restrict__ U,
                            const float* __restrict__ p,
                            const float* __restrict__ V) {
    __shared__ float sc[NREFL];          // c_k, application order

    const int tid  = threadIdx.x;
    const int w    = tid >> 5;
    const int lane = tid & 31;

    if (tid == 0) g_work = 0u;

    if (tid < INSIZE) {
        float pv = p[tid];
        float s = 1.0f / (1.0f + expf(-pv));
        g_sigma[tid] = 0.4f * s + 0.6f;  // 2R(sigmoid-0.5)+mean, R=0.2
    }

    // Norms: warp w (<20) handles U row w (app idx w) and V row w (app 39-w).
    if (w < 20) {
        float su = 0.0f, sv = 0.0f;
        for (int j = lane; j < INSIZE; j += 32) {
            float uu = U[(size_t)w * INSIZE + j]; su += uu * uu;
            float vv = V[(size_t)w * INSIZE + j]; sv += vv * vv;
        }
        #pragma unroll
        for (int off = 16; off; off >>= 1) {
            su += __shfl_xor_sync(0xffffffffu, su, off);
            sv += __shfl_xor_sync(0xffffffffu, sv, off);
        }
        if (lane == 0) {
            sc[w]      = 2.0f / su;
            sc[39 - w] = 2.0f / sv;
        }
    }
    __syncthreads();

    if (tid < NREFL) g_c[tid] = sc[tid];

    // Scaled Gram: flat space of NBLK*25 slots (b, m, j); only m < j computed.
    for (int pid = w; pid < NBLK * BLKR * BLKR; pid += 32) {
        int b   = pid / (BLKR * BLKR);
        int rem = pid % (BLKR * BLKR);
        int m   = rem / BLKR;
        int j   = rem % BLKR;
        if (m >= j) continue;
        const float* ym = yrow(b * BLKR + m, U, V);
        const float* yj = yrow(b * BLKR + j, U, V);
        float s = 0.0f;
        for (int e = lane; e < INSIZE; e += 32) s += ym[e] * yj[e];
        #pragma unroll
        for (int off = 16; off; off >>= 1)
            s += __shfl_xor_sync(0xffffffffu, s, off);
        if (lane == 0) g_G[b][rem] = s * sc[b * BLKR + j];
    }
}

// ---------------------------------------------------------------------------
// Main: persistent, 1 CTA/SM, rows in registers, blocked reflector apply.
// ---------------------------------------------------------------------------
extern __shared__ float smem[];

// Apply one block of 5 reflectors to 4 register-resident rows.
// j-major sweeps keep the live register set small (no 8xfloat4 y buffer).
__device__ __forceinline__ void block_apply(F4U xr[ROWS_PW][8],
                                            const float* __restrict__ sYb,
                                            const float* __restrict__ sGb,
                                            const float* __restrict__ sCb,
                                            int lane) {
    // ---- dots: acc[r][c] accumulates x_r . y_c, one packed chain each ----
    ull acc[ROWS_PW][BLKR];
    #pragma unroll
    for (int r = 0; r < ROWS_PW; r++)
        #pragma unroll
        for (int c = 0; c < BLKR; c++) acc[r][c] = 0ull;

    #pragma unroll
    for (int j = 0; j < 8; j++) {
        F4U y[BLKR];
        #pragma unroll
        for (int c = 0; c < BLKR; c++)
            y[c].f = reinterpret_cast<const float4*>(sYb + c * INSIZE)
                         [lane + 32 * j];
        #pragma unroll
        for (int c = 0; c < BLKR; c++) {
            #pragma unroll
            for (int r = 0; r < ROWS_PW; r++) {
                acc[r][c] = ffma2(xr[r][j].p[0], y[c].p[0], acc[r][c]);
                acc[r][c] = ffma2(xr[r][j].p[1], y[c].p[1], acc[r][c]);
            }
        }
    }

    float d[ROWS_PW][BLKR];
    #pragma unroll
    for (int r = 0; r < ROWS_PW; r++)
        #pragma unroll
        for (int c = 0; c < BLKR; c++) {
            U2 t; t.u = acc[r][c];
            d[r][c] = t.f[0] + t.f[1];
        }

    // ---- batched butterfly: 20 independent shuffles per stage ----
    #pragma unroll
    for (int off = 16; off; off >>= 1) {
        #pragma unroll
        for (int r = 0; r < ROWS_PW; r++)
            #pragma unroll
            for (int c = 0; c < BLKR; c++)
                d[r][c] += __shfl_xor_sync(0xffffffffu, d[r][c], off);
    }

    // ---- forward substitution (exact sequential algorithm, dots hoisted):
    //      s_j = c_j * d_j - sum_{m<j} Gs[m][j] * s_m,  Gs pre-scaled by c_j.
    #pragma unroll
    for (int j = 0; j < BLKR; j++) {
        const float cj = sCb[j];
        float a0 = cj * d[0][j];
        float a1 = cj * d[1][j];
        float a2 = cj * d[2][j];
        float a3 = cj * d[3][j];
        #pragma unroll
        for (int m = 0; m < j; m++) {
            const float g = sGb[m * BLKR + j];
            a0 -= g * d[0][m];
            a1 -= g * d[1][m];
            a2 -= g * d[2][m];
            a3 -= g * d[3][m];
        }
        d[0][j] = a0; d[1][j] = a1; d[2][j] = a2; d[3][j] = a3;
    }

    // ---- pack -s into broadcast pairs (d dies here) ----
    ull ns[ROWS_PW][BLKR];
    #pragma unroll
    for (int r = 0; r < ROWS_PW; r++)
        #pragma unroll
        for (int c = 0; c < BLKR; c++) {
            U2 t; t.f[0] = -d[r][c]; t.f[1] = t.f[0];
            ns[r][c] = t.u;
        }

    // ---- axpy sweep: xr -= s_c * y_c ----
    #pragma unroll
    for (int j = 0; j < 8; j++) {
        F4U y[BLKR];
        #pragma unroll
        for (int c = 0; c < BLKR; c++)
            y[c].f = reinterpret_cast<const float4*>(sYb + c * INSIZE)
                         [lane + 32 * j];
        #pragma unroll
        for (int c = 0; c < BLKR; c++) {
            #pragma unroll
            for (int r = 0; r < ROWS_PW; r++) {
                xr[r][j].p[0] = ffma2(y[c].p[0], ns[r][c], xr[r][j].p[0]);
                xr[r][j].p[1] = ffma2(y[c].p[1], ns[r][c], xr[r][j].p[1]);
            }
        }
    }
}

__global__ void __launch_bounds__(256, 1)
spectral_kernel(const float* __restrict__ x,
                const float* __restrict__ U,
                const float* __restrict__ V,
                const float* __restrict__ bias,
                float* __restrict__ out) {
    float* sY    = smem;                          // 40*1024
    float* sSig  = sY + NREFL * INSIZE;           // 1024
    float* sBias = sSig + INSIZE;                 // 1024
    float* sG    = sBias + INSIZE;                // NBLK*25 = 200
    float* sC    = sG + NBLK * BLKR * BLKR;       // 40

    const int tid = threadIdx.x;

    // Stage reflectors in application order (V rows reversed).
    for (int idx = tid; idx < NREFL * (INSIZE / 4); idx += 256) {
        int row = idx >> 8;              // 256 float4 per row
        int c4  = idx & 255;
        const float4* src = reinterpret_cast<const float4*>(yrow(row, U, V));
        reinterpret_cast<float4*>(sY)[idx] = src[c4];
    }
    if (tid < 256) {
        reinterpret_cast<float4*>(sSig)[tid]  =
            reinterpret_cast<const float4*>(g_sigma)[tid];
        reinterpret_cast<float4*>(sBias)[tid] =
            reinterpret_cast<const float4*>(bias)[tid];
    }
    for (int i = tid; i < NBLK * BLKR * BLKR; i += 256)
        sG[i] = (&g_G[0][0])[i];
    if (tid < NREFL) sC[tid] = g_c[tid];
    __syncthreads();

    const int lane = tid & 31;

    for (;;) {
        unsigned int b;
        if (lane == 0) b = atomicAdd(&g_work, 1u);
        b = __shfl_sync(0xffffffffu, b, 0);
        if (b >= NBATCH) break;

        const int row0 = (int)b * ROWS_PW;

        F4U xr[ROWS_PW][8];
        #pragma unroll
        for (int r = 0; r < ROWS_PW; r++) {
            const float4* xp =
                reinterpret_cast<const float4*>(x + (size_t)(row0 + r) * INSIZE);
            #pragma unroll
            for (int j = 0; j < 8; j++) xr[r][j].f = xp[lane + 32 * j];
        }

        #pragma unroll 1
        for (int blk = 0; blk < NBLK; blk++) {
            if (blk == NBLK / 2) {
                // diagonal sigma between U and V phases
                const float4* sp = reinterpret_cast<const float4*>(sSig);
                #pragma unroll
                for (int j = 0; j < 8; j++) {
                    float4 sg = sp[lane + 32 * j];
                    #pragma unroll
                    for (int r = 0; r < ROWS_PW; r++) {
                        xr[r][j].s[0] *= sg.x; xr[r][j].s[1] *= sg.y;
                        xr[r][j].s[2] *= sg.z; xr[r][j].s[3] *= sg.w;
                    }
                }
            }
            block_apply(xr, sY + (size_t)blk * BLKR * INSIZE,
                        sG + blk * BLKR * BLKR, sC + blk * BLKR, lane);
        }

        // bias add + store
        #pragma unroll
        for (int r = 0; r < ROWS_PW; r++) {
            float4* op =
                reinterpret_cast<float4*>(out + (size_t)(row0 + r) * INSIZE);
            const float4* bp = reinterpret_cast<const float4*>(sBias);
            #pragma unroll
            for (int j = 0; j < 8; j++) {
                float4 v = xr[r][j].f;
                float4 bb = bp[lane + 32 * j];
                v.x += bb.x; v.y += bb.y; v.z += bb.z; v.w += bb.w;
                op[lane + 32 * j] = v;
            }
        }
    }
}

// ---------------------------------------------------------------------------
extern "C" void kernel_launch(void* const* d_in, const int* in_sizes, int n_in,
                              void* d_out, int out_size) {
    const float* x    = (const float*)d_in[0];
    const float* U    = (const float*)d_in[1];
    const float* p    = (const float*)d_in[2];
    const float* V    = (const float*)d_in[3];
    const float* bias = (const float*)d_in[4];
    float* out = (float*)d_out;

    (void)in_sizes; (void)n_in; (void)out_size;

    prep_kernel<<<1, 1024>>>(U, p, V);

    int nsm = 148;
    cudaDeviceGetAttribute(&nsm, cudaDevAttrMultiProcessorCount, 0);

    size_t smem_bytes =
        (size_t)(NREFL * INSIZE + 2 * INSIZE + NBLK * BLKR * BLKR + NREFL) *
        sizeof(float);
    cudaFuncSetAttribute(spectral_kernel,
                         cudaFuncAttributeMaxDynamicSharedMemorySize,
                         (int)smem_bytes);

    spectral_kernel<<<nsm, 256, smem_bytes>>>(x, U, V, bias, out);
}